// round 12
// baseline (speedup 1.0000x reference)
#include <cuda_runtime.h>
#include <cuda_bf16.h>
#include <cstdint>
#include <math.h>

#define NN 50000
#define EE 800000
#define FF 64

// ---------------- scratch (device globals; no allocation allowed) ----------------
__device__ float g_h[NN * FF];                // current node features
__device__ float g_AB[NN * 2 * FF];           // per-node A (cols 0..63) and B (cols 64..127)
__device__ float g_cat[(size_t)NN * 5 * FF];  // [N,320] fused features
__device__ int   g_deg[NN];
__device__ int   g_ptr[NN + 1];
__device__ int   g_cur[NN];
__device__ int   g_csrc[EE];
__device__ float g_Pb[2][FF];                 // folded bias (post_b @ lin_W + lin_b)
// bf16 hi/lo split, transposed weight images Wt[n][k]:
// img 0: W0t   [64][128]   (8192)
// img 1: Wab0t [128][64]   (8192)
// img 2: Wab1t [128][64]   (8192)
// img 3: PW0t  [64][320]   (20480)
// img 4: PW1t  [64][320]   (20480)
__device__ __nv_bfloat16 g_Wsp[2][5][20480];

// ---------------- helpers ----------------
__device__ __forceinline__ void mma_bf16(float* c, const uint32_t* a, const uint32_t* b) {
    asm volatile(
        "mma.sync.aligned.m16n8k16.row.col.f32.bf16.bf16.f32 "
        "{%0,%1,%2,%3}, {%4,%5,%6,%7}, {%8,%9}, {%0,%1,%2,%3};"
        : "+f"(c[0]), "+f"(c[1]), "+f"(c[2]), "+f"(c[3])
        : "r"(a[0]), "r"(a[1]), "r"(a[2]), "r"(a[3]), "r"(b[0]), "r"(b[1]));
}
__device__ __forceinline__ void cvt_split(float2 v, uint32_t& hi, uint32_t& lo) {
    __nv_bfloat16 hx = __float2bfloat16_rn(v.x), hy = __float2bfloat16_rn(v.y);
    __nv_bfloat16 lx = __float2bfloat16_rn(v.x - __bfloat162float(hx));
    __nv_bfloat16 ly = __float2bfloat16_rn(v.y - __bfloat162float(hy));
    __nv_bfloat162 h(hx, hy), l(lx, ly);
    hi = *reinterpret_cast<uint32_t*>(&h);
    lo = *reinterpret_cast<uint32_t*>(&l);
}
__device__ __forceinline__ const float* resolve_src(int id, const float* ext) {
    switch (id) {
        case 0: return g_h;
        case 2: return g_cat;
        default: return ext;
    }
}
__device__ __forceinline__ float* resolve_dst(int id) {
    switch (id) {
        case 0: return g_h;
        default: return g_AB;
    }
}

// ---------------- fused prep ----------------
// blocks: [0,196) zero deg | [196,198) Pb | [198,230) W0t | [230,262) Wab0t
//         [262,294) Wab1t | [294,374) PW0t | [374,454) PW1t
__global__ void k_prep(const float* __restrict__ W0,
                       const float* __restrict__ preW1, const float* __restrict__ preW2,
                       const float* __restrict__ postW1, const float* __restrict__ postb1,
                       const float* __restrict__ linW1, const float* __restrict__ linb1,
                       const float* __restrict__ postW2, const float* __restrict__ postb2,
                       const float* __restrict__ linW2, const float* __restrict__ linb2) {
    int b = blockIdx.x, tid = threadIdx.x;
    if (b < 196) {
        int i = b * 256 + tid;
        if (i < NN) g_deg[i] = 0;
        return;
    }
    if (b < 198) {  // folded bias: Pb = post_b @ lin_W + lin_b
        int layer = b - 196;
        const float* postb = layer ? postb2 : postb1;
        const float* linW  = layer ? linW2  : linW1;
        const float* linb  = layer ? linb2  : linb1;
        if (tid < 64) {
            float s = linb[tid];
            #pragma unroll 8
            for (int k = 0; k < 64; k++) s += postb[k] * linW[k * 64 + tid];
            g_Pb[layer][tid] = s;
        }
        return;
    }
    float v;
    int img, idx;
    if (b < 230) {          // W0t[n][k] = W0[k][n], n<64, k<128
        img = 0;
        idx = (b - 198) * 256 + tid;       // < 8192
        int n = idx >> 7, k = idx & 127;
        v = W0[k * 64 + n];
    } else if (b < 294) {   // Wabt[n][k]: n<128 output col, k<64 input
        int layer = (b < 262) ? 0 : 1;
        const float* preW = layer ? preW2 : preW1;
        img = 1 + layer;
        idx = (b - (layer ? 262 : 230)) * 256 + tid;   // < 8192
        int n = idx >> 6, k = idx & 63;
        v = (n < 64) ? preW[k * 64 + n] : preW[(64 + k) * 64 + (n - 64)];
    } else {                // PWt[n][k] = sum_j postW[k][j] * linW[j][n], n<64, k<320
        int layer = (b < 374) ? 0 : 1;
        const float* postW = layer ? postW2 : postW1;
        const float* linW  = layer ? linW2  : linW1;
        img = 3 + layer;
        idx = (b - (layer ? 374 : 294)) * 256 + tid;   // < 20480
        int n = idx / 320, k = idx % 320;
        v = 0.f;
        #pragma unroll 8
        for (int j = 0; j < 64; j++) v += postW[k * 64 + j] * linW[j * 64 + n];
    }
    __nv_bfloat16 hi = __float2bfloat16_rn(v);
    __nv_bfloat16 lo = __float2bfloat16_rn(v - __bfloat162float(hi));
    g_Wsp[0][img][idx] = hi;
    g_Wsp[1][img][idx] = lo;
}

// ---------------- CSR build ----------------
__global__ void k_deg(const int* __restrict__ dst) {
    int e = blockIdx.x * blockDim.x + threadIdx.x;
    if (e < EE) atomicAdd(&g_deg[dst[e]], 1);
}

__global__ void k_scan() {  // single block, 1024 threads, shfl-based
    __shared__ int wsum[32];
    __shared__ int carry_s;
    int tid = threadIdx.x, lane = tid & 31, wid = tid >> 5;
    if (tid == 0) { carry_s = 0; g_ptr[0] = 0; }
    __syncthreads();
    for (int base = 0; base < NN; base += 1024) {
        int i = base + tid;
        int v = (i < NN) ? g_deg[i] : 0;
        int x = v;
        #pragma unroll
        for (int off = 1; off < 32; off <<= 1) {
            int y = __shfl_up_sync(0xffffffffu, x, off);
            if (lane >= off) x += y;
        }
        if (lane == 31) wsum[wid] = x;
        __syncthreads();
        if (wid == 0) {
            int s = wsum[lane];
            #pragma unroll
            for (int off = 1; off < 32; off <<= 1) {
                int y = __shfl_up_sync(0xffffffffu, s, off);
                if (lane >= off) s += y;
            }
            wsum[lane] = s;
        }
        __syncthreads();
        int incl = x + (wid ? wsum[wid - 1] : 0) + carry_s;
        if (i < NN) { g_ptr[i + 1] = incl; g_cur[i] = incl - v; }
        __syncthreads();
        if (tid == 1023) carry_s = incl;
        __syncthreads();
    }
}

__global__ void k_fill(const int* __restrict__ src, const int* __restrict__ dst) {
    int e = blockIdx.x * blockDim.x + threadIdx.x;
    if (e < EE) {
        int slot = atomicAdd(&g_cur[dst[e]], 1);
        g_csrc[slot] = src[e];
    }
}

// ---------------- generic HMMA GEMM: A[N,K] @ Wt(img) -> NCOL cols ----------------
// 256 threads = 8 warps; block tile 128 rows; warp tile 16 rows x NCOL cols.
// W staged per k-chunk in padded SMEM (WSTR = KCH/2+4 words: 36/68/84, all ≡4 mod 8
// -> lane bank gr*(WSTR%32)+qc hits all 32 banks, conflict-free).
// 3-product split-precision: hi*hi + lo*hi + hi*lo (error ~ eps^2 ~ 1.5e-5).
// ACT: 0 none, 1 leaky(0.2), 2 relu.  BID: -2 none, -1 ext, 0/1 g_Pb.  FINAL: fuse W2 head.
template <int K, int NCOL, int IMG, int AID, int BID, int ACT, int OID, int FINAL>
__global__ void __launch_bounds__(256) k_mma(const float* __restrict__ Aext,
                                             const float* __restrict__ biasExt,
                                             const float* __restrict__ W2,
                                             const float* __restrict__ b2,
                                             float* __restrict__ outp) {
    constexpr int NT = NCOL / 8;
    constexpr int KCH = (K > 160) ? 160 : K;
    constexpr int NCHUNK = K / KCH;
    constexpr int KS = KCH / 16;
    constexpr int WSTR = KCH / 2 + 4;
    __shared__ uint32_t Wsh[2][NCOL * WSTR];

    const float* A = resolve_src(AID, Aext);
    const float* bias = (BID == -2) ? (const float*)0
                       : ((BID == -1) ? biasExt : g_Pb[BID < 0 ? 0 : BID]);
    float* C = resolve_dst(OID);

    int tid = threadIdx.x, wid = tid >> 5, lane = tid & 31;
    int gr = lane >> 2, qc = lane & 3;
    int ra = blockIdx.x * 128 + wid * 16 + gr;
    int rb = ra + 8;
    bool va = ra < NN, vb = rb < NN;
    const float* rowa = A + (size_t)ra * K;
    const float* rowb = A + (size_t)rb * K;
    const uint32_t* srcH = reinterpret_cast<const uint32_t*>(g_Wsp[0][IMG]);
    const uint32_t* srcL = reinterpret_cast<const uint32_t*>(g_Wsp[1][IMG]);

    float acc[NT][4] = {};
    for (int ch = 0; ch < NCHUNK; ch++) {
        if (ch) __syncthreads();
        // stage this k-chunk of W (NCOL rows x KCH/2 words per mat), coalesced
        constexpr int WORDS = NCOL * (KCH / 2);
        for (int idx = tid; idx < WORDS; idx += 256) {
            int n = idx / (KCH / 2);
            int kw = idx - n * (KCH / 2);
            Wsh[0][n * WSTR + kw] = srcH[n * (K / 2) + ch * (KCH / 2) + kw];
            Wsh[1][n * WSTR + kw] = srcL[n * (K / 2) + ch * (KCH / 2) + kw];
        }
        __syncthreads();
        #pragma unroll 2
        for (int ksl = 0; ksl < KS; ksl++) {
            int k0 = ch * KCH + ksl * 16 + qc * 2;
            float2 z = make_float2(0.f, 0.f);
            float2 a00 = va ? *reinterpret_cast<const float2*>(rowa + k0)     : z;
            float2 a01 = va ? *reinterpret_cast<const float2*>(rowa + k0 + 8) : z;
            float2 a10 = vb ? *reinterpret_cast<const float2*>(rowb + k0)     : z;
            float2 a11 = vb ? *reinterpret_cast<const float2*>(rowb + k0 + 8) : z;
            uint32_t ah[4], al[4];
            cvt_split(a00, ah[0], al[0]);
            cvt_split(a10, ah[1], al[1]);
            cvt_split(a01, ah[2], al[2]);
            cvt_split(a11, ah[3], al[3]);
            int kw = ksl * 8 + qc;
            #pragma unroll
            for (int nt = 0; nt < NT; nt++) {
                int n = nt * 8 + gr;
                uint32_t bh[2], bl[2];
                bh[0] = Wsh[0][n * WSTR + kw];
                bh[1] = Wsh[0][n * WSTR + kw + 4];
                bl[0] = Wsh[1][n * WSTR + kw];
                bl[1] = Wsh[1][n * WSTR + kw + 4];
                mma_bf16(acc[nt], ah, bh);
                mma_bf16(acc[nt], al, bh);
                mma_bf16(acc[nt], ah, bl);
            }
        }
    }

    if (FINAL) {
        // out[row] = sum_col relu(acc + bias[col]) * W2[col] + b2   (NCOL must be 64)
        float pa = 0.f, pb = 0.f;
        #pragma unroll
        for (int nt = 0; nt < NT; nt++) {
            int col = nt * 8 + qc * 2;
            float pb0 = bias[col], pb1 = bias[col + 1];
            float w0 = W2[col], w1 = W2[col + 1];
            pa = fmaf(fmaxf(acc[nt][0] + pb0, 0.f), w0, pa);
            pa = fmaf(fmaxf(acc[nt][1] + pb1, 0.f), w1, pa);
            pb = fmaf(fmaxf(acc[nt][2] + pb0, 0.f), w0, pb);
            pb = fmaf(fmaxf(acc[nt][3] + pb1, 0.f), w1, pb);
        }
        pa += __shfl_xor_sync(0xffffffffu, pa, 1);
        pa += __shfl_xor_sync(0xffffffffu, pa, 2);
        pb += __shfl_xor_sync(0xffffffffu, pb, 1);
        pb += __shfl_xor_sync(0xffffffffu, pb, 2);
        if (qc == 0) {
            float bv = b2[0];
            if (va) outp[ra] = pa + bv;
            if (vb) outp[rb] = pb + bv;
        }
    } else {
        #pragma unroll
        for (int nt = 0; nt < NT; nt++) {
            int col = nt * 8 + qc * 2;
            float b0v = 0.f, b1v = 0.f;
            if (BID != -2) { b0v = bias[col]; b1v = bias[col + 1]; }
            float v0 = acc[nt][0] + b0v, v1 = acc[nt][1] + b1v;
            float v2 = acc[nt][2] + b0v, v3 = acc[nt][3] + b1v;
            if (ACT == 1) {
                v0 = (v0 > 0.f) ? v0 : 0.2f * v0;
                v1 = (v1 > 0.f) ? v1 : 0.2f * v1;
                v2 = (v2 > 0.f) ? v2 : 0.2f * v2;
                v3 = (v3 > 0.f) ? v3 : 0.2f * v3;
            }
            if (ACT == 2) {
                v0 = fmaxf(v0, 0.f); v1 = fmaxf(v1, 0.f);
                v2 = fmaxf(v2, 0.f); v3 = fmaxf(v3, 0.f);
            }
            if (va) *reinterpret_cast<float2*>(&C[(size_t)ra * NCOL + col]) = make_float2(v0, v1);
            if (vb) *reinterpret_cast<float2*>(&C[(size_t)rb * NCOL + col]) = make_float2(v2, v3);
        }
    }
}

// ---------------- aggregation: segment sum/max of B over rank-sorted CSR, build cat --------
#define MAXD 192
__global__ void __launch_bounds__(256) k_agg(const float* __restrict__ preb) {
    __shared__ int ssrc[4][MAXD];
    __shared__ int ssrt[4][MAXD];
    int g = threadIdx.x >> 6;
    int t = threadIdx.x & 63;
    int node = blockIdx.x * 4 + g;
    bool valid = node < NN;
    int beg = 0, end = 0;
    if (valid) { beg = g_ptr[node]; end = g_ptr[node + 1]; }
    int deg = end - beg;
    bool small = valid && (deg <= MAXD);
    if (small) {
        for (int e = t; e < deg; e += 64) ssrc[g][e] = g_csrc[beg + e];
    }
    __syncthreads();
    if (small) {
        for (int i = t; i < deg; i += 64) {
            int v = ssrc[g][i];
            int rank = 0;
            for (int j = 0; j < deg; j++) {
                int u = ssrc[g][j];
                rank += (u < v) || (u == v && j < i);
            }
            ssrt[g][rank] = v;
        }
    }
    __syncthreads();
    if (!valid) return;
    float sum = 0.f, mx = -3.4e38f;
    if (small) {
        #pragma unroll 4
        for (int e = 0; e < deg; e++) {
            float v = g_AB[(size_t)ssrt[g][e] * 128 + 64 + t];
            sum += v;
            mx = fmaxf(mx, v);
        }
    } else {
        for (int e = beg; e < end; e++) {
            float v = g_AB[(size_t)g_csrc[e] * 128 + 64 + t];
            sum += v;
            mx = fmaxf(mx, v);
        }
    }
    float hx = g_h[node * 64 + t];
    float* cr = &g_cat[(size_t)node * 320];
    cr[t] = hx;
    if (deg == 0) {
        cr[64 + t] = 0.f; cr[128 + t] = 0.f; cr[192 + t] = 0.f; cr[256 + t] = 0.f;
    } else {
        float bA = g_AB[(size_t)node * 128 + t] + preb[t];
        float mean = bA + sum / (float)deg;
        float mxv = bA + mx;
        float sa = 2.8332133440562162f / logf((float)deg + 1.0f);  // log(17)/log(deg+1)
        float sl = (float)deg * 0.0625f;                            // deg/16
        cr[64 + t] = mean * sa;
        cr[128 + t] = mxv * sa;
        cr[192 + t] = mean * sl;
        cr[256 + t] = mxv * sl;
    }
}

// ---------------- launch: kernel launches ONLY ----------------
extern "C" void kernel_launch(void* const* d_in, const int* in_sizes, int n_in,
                              void* d_out, int out_size) {
    (void)in_sizes; (void)n_in; (void)out_size;
    const float* x   = (const float*)d_in[0];
    const int*   ei  = (const int*)d_in[2];
    const float* W0  = (const float*)d_in[3];
    const float* b0  = (const float*)d_in[4];
    const float* preW1  = (const float*)d_in[5];
    const float* preB1  = (const float*)d_in[6];
    const float* postW1 = (const float*)d_in[7];
    const float* postB1 = (const float*)d_in[8];
    const float* linW1  = (const float*)d_in[9];
    const float* linB1  = (const float*)d_in[10];
    const float* preW2  = (const float*)d_in[11];
    const float* preB2  = (const float*)d_in[12];
    const float* postW2 = (const float*)d_in[13];
    const float* postB2 = (const float*)d_in[14];
    const float* linW2  = (const float*)d_in[15];
    const float* linB2  = (const float*)d_in[16];
    const float* W2 = (const float*)d_in[17];
    const float* b2 = (const float*)d_in[18];
    float* out = (float*)d_out;

    const int* src = ei;
    const int* dst = ei + EE;
    const int GB = (NN + 127) / 128;   // 391

    // prep + CSR build
    k_prep<<<454, 256>>>(W0, preW1, preW2, postW1, postB1, linW1, linB1,
                         postW2, postB2, linW2, linB2);
    k_deg<<<(EE + 255) / 256, 256>>>(dst);
    k_scan<<<1, 1024>>>();
    k_fill<<<(EE + 255) / 256, 256>>>(src, dst);

    // h0 = leaky_relu(x @ W0 + b0)        K=128 NCOL=64  img0  A=ext  bias=ext  leaky -> g_h
    k_mma<128, 64, 0, -1, -1, 1, 0, 0><<<GB, 256>>>(x, b0, 0, 0, 0);

    // layer 1
    k_mma<64, 128, 1, 0, -2, 0, 1, 0><<<GB, 256>>>(0, 0, 0, 0, 0);      // g_h @ Wab0 -> g_AB
    k_agg<<<(NN + 3) / 4, 256>>>(preB1);
    k_mma<320, 64, 3, 2, 0, 2, 0, 0><<<GB, 256>>>(0, 0, 0, 0, 0);       // cat @ PW0 +Pb0 relu -> g_h

    // layer 2 (final fuses relu + out = h . W2 + b2)
    k_mma<64, 128, 2, 0, -2, 0, 1, 0><<<GB, 256>>>(0, 0, 0, 0, 0);      // g_h @ Wab1 -> g_AB
    k_agg<<<(NN + 3) / 4, 256>>>(preB2);
    k_mma<320, 64, 4, 2, 1, 2, 0, 1><<<GB, 256>>>(0, 0, W2, b2, out);   // cat @ PW1 -> out
}

// round 16
// speedup vs baseline: 1.4297x; 1.4297x over previous
#include <cuda_runtime.h>
#include <cuda_bf16.h>
#include <cstdint>
#include <math.h>

#define NN 50000
#define EE 800000
#define FF 64

// ---------------- scratch (device globals; no allocation allowed) ----------------
__device__ float g_h[NN * FF];                // current node features
__device__ float g_AB[NN * 2 * FF];           // per-node A (cols 0..63) and B (cols 64..127)
__device__ float g_cat[(size_t)NN * 5 * FF];  // [N,320] fused features
__device__ int   g_deg[NN];
__device__ int   g_ptr[NN + 1];
__device__ int   g_cur[NN];
__device__ int   g_csrc[EE];
__device__ float g_Pb[2][FF];                 // folded bias (post_b @ lin_W + lin_b)
// bf16 hi/lo split, transposed weight images Wt[n][k]:
// img 0: W0t   [64][128]   (8192)
// img 1: Wab0t [128][64]   (8192)
// img 2: Wab1t [128][64]   (8192)
// img 3: PW0t  [64][320]   (20480)
// img 4: PW1t  [64][320]   (20480)
__device__ __nv_bfloat16 g_Wsp[2][5][20480];

// ---------------- helpers ----------------
__device__ __forceinline__ void mma_bf16(float* c, const uint32_t* a, const uint32_t* b) {
    asm volatile(
        "mma.sync.aligned.m16n8k16.row.col.f32.bf16.bf16.f32 "
        "{%0,%1,%2,%3}, {%4,%5,%6,%7}, {%8,%9}, {%0,%1,%2,%3};"
        : "+f"(c[0]), "+f"(c[1]), "+f"(c[2]), "+f"(c[3])
        : "r"(a[0]), "r"(a[1]), "r"(a[2]), "r"(a[3]), "r"(b[0]), "r"(b[1]));
}
__device__ __forceinline__ void cvt_split(float2 v, uint32_t& hi, uint32_t& lo) {
    __nv_bfloat16 hx = __float2bfloat16_rn(v.x), hy = __float2bfloat16_rn(v.y);
    __nv_bfloat16 lx = __float2bfloat16_rn(v.x - __bfloat162float(hx));
    __nv_bfloat16 ly = __float2bfloat16_rn(v.y - __bfloat162float(hy));
    __nv_bfloat162 h(hx, hy), l(lx, ly);
    hi = *reinterpret_cast<uint32_t*>(&h);
    lo = *reinterpret_cast<uint32_t*>(&l);
}
__device__ __forceinline__ const float* resolve_src(int id, const float* ext) {
    switch (id) {
        case 0: return g_h;
        case 2: return g_cat;
        default: return ext;
    }
}
__device__ __forceinline__ float* resolve_dst(int id) {
    switch (id) {
        case 0: return g_h;
        default: return g_AB;
    }
}

// ---------------- fused prep ----------------
// blocks: [0,196) zero deg | [196,198) Pb | [198,230) W0t | [230,262) Wab0t
//         [262,294) Wab1t | [294,374) PW0t | [374,454) PW1t
__global__ void k_prep(const float* __restrict__ W0,
                       const float* __restrict__ preW1, const float* __restrict__ preW2,
                       const float* __restrict__ postW1, const float* __restrict__ postb1,
                       const float* __restrict__ linW1, const float* __restrict__ linb1,
                       const float* __restrict__ postW2, const float* __restrict__ postb2,
                       const float* __restrict__ linW2, const float* __restrict__ linb2) {
    int b = blockIdx.x, tid = threadIdx.x;
    if (b < 196) {
        int i = b * 256 + tid;
        if (i < NN) g_deg[i] = 0;
        return;
    }
    if (b < 198) {  // folded bias: Pb = post_b @ lin_W + lin_b
        int layer = b - 196;
        const float* postb = layer ? postb2 : postb1;
        const float* linW  = layer ? linW2  : linW1;
        const float* linb  = layer ? linb2  : linb1;
        if (tid < 64) {
            float s = linb[tid];
            #pragma unroll 8
            for (int k = 0; k < 64; k++) s += postb[k] * linW[k * 64 + tid];
            g_Pb[layer][tid] = s;
        }
        return;
    }
    float v;
    int img, idx;
    if (b < 230) {          // W0t[n][k] = W0[k][n], n<64, k<128
        img = 0;
        idx = (b - 198) * 256 + tid;       // < 8192
        int n = idx >> 7, k = idx & 127;
        v = W0[k * 64 + n];
    } else if (b < 294) {   // Wabt[n][k]: n<128 output col, k<64 input
        int layer = (b < 262) ? 0 : 1;
        const float* preW = layer ? preW2 : preW1;
        img = 1 + layer;
        idx = (b - (layer ? 262 : 230)) * 256 + tid;   // < 8192
        int n = idx >> 6, k = idx & 63;
        v = (n < 64) ? preW[k * 64 + n] : preW[(64 + k) * 64 + (n - 64)];
    } else {                // PWt[n][k] = sum_j postW[k][j] * linW[j][n], n<64, k<320
        int layer = (b < 374) ? 0 : 1;
        const float* postW = layer ? postW2 : postW1;
        const float* linW  = layer ? linW2  : linW1;
        img = 3 + layer;
        idx = (b - (layer ? 374 : 294)) * 256 + tid;   // < 20480
        int n = idx / 320, k = idx % 320;
        v = 0.f;
        #pragma unroll 8
        for (int j = 0; j < 64; j++) v += postW[k * 64 + j] * linW[j * 64 + n];
    }
    __nv_bfloat16 hi = __float2bfloat16_rn(v);
    __nv_bfloat16 lo = __float2bfloat16_rn(v - __bfloat162float(hi));
    g_Wsp[0][img][idx] = hi;
    g_Wsp[1][img][idx] = lo;
}

// ---------------- CSR build ----------------
__global__ void k_deg(const int* __restrict__ dst) {
    int e = blockIdx.x * blockDim.x + threadIdx.x;
    if (e < EE) atomicAdd(&g_deg[dst[e]], 1);
}

__global__ void k_scan() {  // single block, 1024 threads, shfl-based
    __shared__ int wsum[32];
    __shared__ int carry_s;
    int tid = threadIdx.x, lane = tid & 31, wid = tid >> 5;
    if (tid == 0) { carry_s = 0; g_ptr[0] = 0; }
    __syncthreads();
    for (int base = 0; base < NN; base += 1024) {
        int i = base + tid;
        int v = (i < NN) ? g_deg[i] : 0;
        int x = v;
        #pragma unroll
        for (int off = 1; off < 32; off <<= 1) {
            int y = __shfl_up_sync(0xffffffffu, x, off);
            if (lane >= off) x += y;
        }
        if (lane == 31) wsum[wid] = x;
        __syncthreads();
        if (wid == 0) {
            int s = wsum[lane];
            #pragma unroll
            for (int off = 1; off < 32; off <<= 1) {
                int y = __shfl_up_sync(0xffffffffu, s, off);
                if (lane >= off) s += y;
            }
            wsum[lane] = s;
        }
        __syncthreads();
        int incl = x + (wid ? wsum[wid - 1] : 0) + carry_s;
        if (i < NN) { g_ptr[i + 1] = incl; g_cur[i] = incl - v; }
        __syncthreads();
        if (tid == 1023) carry_s = incl;
        __syncthreads();
    }
}

__global__ void k_fill(const int* __restrict__ src, const int* __restrict__ dst) {
    int e = blockIdx.x * blockDim.x + threadIdx.x;
    if (e < EE) {
        int slot = atomicAdd(&g_cur[dst[e]], 1);
        g_csrc[slot] = src[e];
    }
}

// ---------------- generic HMMA GEMM: A[N,K] @ Wt(img) -> NCOL cols ----------------
// 256 threads = 8 warps. Warp tile is ALWAYS 16 rows x 64 cols (NT=8, acc=32 regs; the
// NT=16 variant spilled to local memory and regressed R12).
//   NCOL=64 : 8 row-groups  -> block tile 128 rows
//   NCOL=128: 4 row-groups x 2 col-halves -> block tile 64 rows
// W staged per k-chunk in padded SMEM (WSTR = KCH/2+4 -> lane bank 4*gr+qc, conflict-free;
// col-half offset 64*WSTR ≡ 0 mod 32 so the pattern is unchanged).
// 3-product split-precision: hi*hi + lo*hi + hi*lo (error ~ eps^2 ~ 1.5e-5).
// ACT: 0 none, 1 leaky(0.2), 2 relu.  BID: -2 none, -1 ext, 0/1 g_Pb.  FINAL: fuse W2 head.
template <int K, int NCOL, int IMG, int AID, int BID, int ACT, int OID, int FINAL>
__global__ void __launch_bounds__(256) k_mma(const float* __restrict__ Aext,
                                             const float* __restrict__ biasExt,
                                             const float* __restrict__ W2,
                                             const float* __restrict__ b2,
                                             float* __restrict__ outp) {
    constexpr int NT = 8;                          // warp covers 64 cols always
    constexpr int ROWS = (NCOL == 128) ? 64 : 128; // rows per block
    constexpr int KCH = (K > 160) ? 160 : K;
    constexpr int NCHUNK = K / KCH;
    constexpr int KS = KCH / 16;
    constexpr int WSTR = KCH / 2 + 4;
    __shared__ uint32_t Wsh[2][NCOL * WSTR];

    const float* A = resolve_src(AID, Aext);
    const float* bias = (BID == -2) ? (const float*)0
                       : ((BID == -1) ? biasExt : g_Pb[BID < 0 ? 0 : BID]);
    float* C = resolve_dst(OID);

    int tid = threadIdx.x, wid = tid >> 5, lane = tid & 31;
    int gr = lane >> 2, qc = lane & 3;
    int rowgrp = (NCOL == 128) ? (wid >> 1) : wid;
    int colofs = (NCOL == 128) ? ((wid & 1) * 64) : 0;
    int ra = blockIdx.x * ROWS + rowgrp * 16 + gr;
    int rb = ra + 8;
    bool va = ra < NN, vb = rb < NN;
    const float* rowa = A + (size_t)ra * K;
    const float* rowb = A + (size_t)rb * K;
    const uint32_t* srcH = reinterpret_cast<const uint32_t*>(g_Wsp[0][IMG]);
    const uint32_t* srcL = reinterpret_cast<const uint32_t*>(g_Wsp[1][IMG]);

    float acc[NT][4] = {};
    for (int ch = 0; ch < NCHUNK; ch++) {
        if (ch) __syncthreads();
        // stage this k-chunk of W (NCOL rows x KCH/2 words per mat), coalesced
        constexpr int WORDS = NCOL * (KCH / 2);
        for (int idx = tid; idx < WORDS; idx += 256) {
            int n = idx / (KCH / 2);
            int kw = idx - n * (KCH / 2);
            Wsh[0][n * WSTR + kw] = srcH[n * (K / 2) + ch * (KCH / 2) + kw];
            Wsh[1][n * WSTR + kw] = srcL[n * (K / 2) + ch * (KCH / 2) + kw];
        }
        __syncthreads();
        #pragma unroll 2
        for (int ksl = 0; ksl < KS; ksl++) {
            int k0 = ch * KCH + ksl * 16 + qc * 2;
            float2 z = make_float2(0.f, 0.f);
            float2 a00 = va ? *reinterpret_cast<const float2*>(rowa + k0)     : z;
            float2 a01 = va ? *reinterpret_cast<const float2*>(rowa + k0 + 8) : z;
            float2 a10 = vb ? *reinterpret_cast<const float2*>(rowb + k0)     : z;
            float2 a11 = vb ? *reinterpret_cast<const float2*>(rowb + k0 + 8) : z;
            uint32_t ah[4], al[4];
            cvt_split(a00, ah[0], al[0]);
            cvt_split(a10, ah[1], al[1]);
            cvt_split(a01, ah[2], al[2]);
            cvt_split(a11, ah[3], al[3]);
            int kw = ksl * 8 + qc;
            #pragma unroll
            for (int nt = 0; nt < NT; nt++) {
                int n = colofs + nt * 8 + gr;
                uint32_t bh[2], bl[2];
                bh[0] = Wsh[0][n * WSTR + kw];
                bh[1] = Wsh[0][n * WSTR + kw + 4];
                bl[0] = Wsh[1][n * WSTR + kw];
                bl[1] = Wsh[1][n * WSTR + kw + 4];
                mma_bf16(acc[nt], ah, bh);
                mma_bf16(acc[nt], al, bh);
                mma_bf16(acc[nt], ah, bl);
            }
        }
    }

    if (FINAL) {
        // out[row] = sum_col relu(acc + bias[col]) * W2[col] + b2   (NCOL must be 64)
        float pa = 0.f, pb = 0.f;
        #pragma unroll
        for (int nt = 0; nt < NT; nt++) {
            int col = nt * 8 + qc * 2;
            float pb0 = bias[col], pb1 = bias[col + 1];
            float w0 = W2[col], w1 = W2[col + 1];
            pa = fmaf(fmaxf(acc[nt][0] + pb0, 0.f), w0, pa);
            pa = fmaf(fmaxf(acc[nt][1] + pb1, 0.f), w1, pa);
            pb = fmaf(fmaxf(acc[nt][2] + pb0, 0.f), w0, pb);
            pb = fmaf(fmaxf(acc[nt][3] + pb1, 0.f), w1, pb);
        }
        pa += __shfl_xor_sync(0xffffffffu, pa, 1);
        pa += __shfl_xor_sync(0xffffffffu, pa, 2);
        pb += __shfl_xor_sync(0xffffffffu, pb, 1);
        pb += __shfl_xor_sync(0xffffffffu, pb, 2);
        if (qc == 0) {
            float bv = b2[0];
            if (va) outp[ra] = pa + bv;
            if (vb) outp[rb] = pb + bv;
        }
    } else {
        #pragma unroll
        for (int nt = 0; nt < NT; nt++) {
            int col = colofs + nt * 8 + qc * 2;
            float b0v = 0.f, b1v = 0.f;
            if (BID != -2) { b0v = bias[col]; b1v = bias[col + 1]; }
            float v0 = acc[nt][0] + b0v, v1 = acc[nt][1] + b1v;
            float v2 = acc[nt][2] + b0v, v3 = acc[nt][3] + b1v;
            if (ACT == 1) {
                v0 = (v0 > 0.f) ? v0 : 0.2f * v0;
                v1 = (v1 > 0.f) ? v1 : 0.2f * v1;
                v2 = (v2 > 0.f) ? v2 : 0.2f * v2;
                v3 = (v3 > 0.f) ? v3 : 0.2f * v3;
            }
            if (ACT == 2) {
                v0 = fmaxf(v0, 0.f); v1 = fmaxf(v1, 0.f);
                v2 = fmaxf(v2, 0.f); v3 = fmaxf(v3, 0.f);
            }
            if (va) *reinterpret_cast<float2*>(&C[(size_t)ra * NCOL + col]) = make_float2(v0, v1);
            if (vb) *reinterpret_cast<float2*>(&C[(size_t)rb * NCOL + col]) = make_float2(v2, v3);
        }
    }
}

// ---------------- aggregation: segment sum/max of B over rank-sorted CSR, build cat --------
#define MAXD 192
__global__ void __launch_bounds__(256) k_agg(const float* __restrict__ preb) {
    __shared__ int ssrc[4][MAXD];
    __shared__ int ssrt[4][MAXD];
    int g = threadIdx.x >> 6;
    int t = threadIdx.x & 63;
    int node = blockIdx.x * 4 + g;
    bool valid = node < NN;
    int beg = 0, end = 0;
    if (valid) { beg = g_ptr[node]; end = g_ptr[node + 1]; }
    int deg = end - beg;
    bool small = valid && (deg <= MAXD);
    if (small) {
        for (int e = t; e < deg; e += 64) ssrc[g][e] = g_csrc[beg + e];
    }
    __syncthreads();
    if (small) {
        for (int i = t; i < deg; i += 64) {
            int v = ssrc[g][i];
            int rank = 0;
            for (int j = 0; j < deg; j++) {
                int u = ssrc[g][j];
                rank += (u < v) || (u == v && j < i);
            }
            ssrt[g][rank] = v;
        }
    }
    __syncthreads();
    if (!valid) return;
    float sum = 0.f, mx = -3.4e38f;
    if (small) {
        #pragma unroll 4
        for (int e = 0; e < deg; e++) {
            float v = g_AB[(size_t)ssrt[g][e] * 128 + 64 + t];
            sum += v;
            mx = fmaxf(mx, v);
        }
    } else {
        for (int e = beg; e < end; e++) {
            float v = g_AB[(size_t)g_csrc[e] * 128 + 64 + t];
            sum += v;
            mx = fmaxf(mx, v);
        }
    }
    float hx = g_h[node * 64 + t];
    float* cr = &g_cat[(size_t)node * 320];
    cr[t] = hx;
    if (deg == 0) {
        cr[64 + t] = 0.f; cr[128 + t] = 0.f; cr[192 + t] = 0.f; cr[256 + t] = 0.f;
    } else {
        float bA = g_AB[(size_t)node * 128 + t] + preb[t];
        float mean = bA + sum / (float)deg;
        float mxv = bA + mx;
        float sa = 2.8332133440562162f / logf((float)deg + 1.0f);  // log(17)/log(deg+1)
        float sl = (float)deg * 0.0625f;                            // deg/16
        cr[64 + t] = mean * sa;
        cr[128 + t] = mxv * sa;
        cr[192 + t] = mean * sl;
        cr[256 + t] = mxv * sl;
    }
}

// ---------------- launch: kernel launches ONLY ----------------
extern "C" void kernel_launch(void* const* d_in, const int* in_sizes, int n_in,
                              void* d_out, int out_size) {
    (void)in_sizes; (void)n_in; (void)out_size;
    const float* x   = (const float*)d_in[0];
    const int*   ei  = (const int*)d_in[2];
    const float* W0  = (const float*)d_in[3];
    const float* b0  = (const float*)d_in[4];
    const float* preW1  = (const float*)d_in[5];
    const float* preB1  = (const float*)d_in[6];
    const float* postW1 = (const float*)d_in[7];
    const float* postB1 = (const float*)d_in[8];
    const float* linW1  = (const float*)d_in[9];
    const float* linB1  = (const float*)d_in[10];
    const float* preW2  = (const float*)d_in[11];
    const float* preB2  = (const float*)d_in[12];
    const float* postW2 = (const float*)d_in[13];
    const float* postB2 = (const float*)d_in[14];
    const float* linW2  = (const float*)d_in[15];
    const float* linB2  = (const float*)d_in[16];
    const float* W2 = (const float*)d_in[17];
    const float* b2 = (const float*)d_in[18];
    float* out = (float*)d_out;

    const int* src = ei;
    const int* dst = ei + EE;
    const int GB128 = (NN + 127) / 128;   // 391 (block tile 128 rows)
    const int GB64  = (NN + 63) / 64;     // 782 (block tile 64 rows, NCOL=128)

    // prep + CSR build
    k_prep<<<454, 256>>>(W0, preW1, preW2, postW1, postB1, linW1, linB1,
                         postW2, postB2, linW2, linB2);
    k_deg<<<(EE + 255) / 256, 256>>>(dst);
    k_scan<<<1, 1024>>>();
    k_fill<<<(EE + 255) / 256, 256>>>(src, dst);

    // h0 = leaky_relu(x @ W0 + b0)
    k_mma<128, 64, 0, -1, -1, 1, 0, 0><<<GB128, 256>>>(x, b0, 0, 0, 0);

    // layer 1
    k_mma<64, 128, 1, 0, -2, 0, 1, 0><<<GB64, 256>>>(0, 0, 0, 0, 0);     // g_h @ Wab0 -> g_AB
    k_agg<<<(NN + 3) / 4, 256>>>(preB1);
    k_mma<320, 64, 3, 2, 0, 2, 0, 0><<<GB128, 256>>>(0, 0, 0, 0, 0);     // cat @ PW0 +Pb0 relu -> g_h

    // layer 2 (final fuses relu + out = h . W2 + b2)
    k_mma<64, 128, 2, 0, -2, 0, 1, 0><<<GB64, 256>>>(0, 0, 0, 0, 0);     // g_h @ Wab1 -> g_AB
    k_agg<<<(NN + 3) / 4, 256>>>(preB2);
    k_mma<320, 64, 4, 2, 1, 2, 0, 1><<<GB128, 256>>>(0, 0, W2, b2, out); // cat @ PW1 -> out
}